// round 11
// baseline (speedup 1.0000x reference)
#include <cuda_runtime.h>
#include <cuda_bf16.h>
#include <cstdint>

// Problem constants
#define M_ROWS 4096
#define K_DIM  256
#define NN     16384
#define KTOP   1638

// GEMM tiling: K processed in two 128-halves so 2 CTAs fit per SM.
#define TR 128
#define TC 128
#define GEMM_THREADS 512
#define HALF_K 128
#define HSLOTS 40                    // per-column per-half CSC capacity
#define NSP (HSLOTS / 2)             // float4 slot-pairs
#define XS_STRIDE 132                // 132*4=528 = 33*16 -> LDS.128 aligned
#define OS_STRIDE 129                // conflict-free column stores
#define XS_FLOATS (HALF_K * XS_STRIDE)          // 16896 floats (67.6 KB)
#define PP_OFF   XS_FLOATS                      // float4-aligned (67584 % 16 == 0)
#define SCNT_OFF (PP_OFF + NSP * TC * 4)        // + 10240 floats (40 KB)
#define GEMM_SMEM ((SCNT_OFF + TC) * 4)         // 109056 B -> 2 CTAs/SM

// ---------------------------------------------------------------------------
// Scratch: per-half CSC of W, [half][slot][n] layout (coalesced everywhere).
// pair = (w, local-k-as-float-bits), local k in [0,128). Tail slots zeroed by
// the build kernel itself => inert in FMA, no separate zero pass.
// ---------------------------------------------------------------------------
__device__ float2 g_pairT[(size_t)2 * HSLOTS * NN];   // 10.5 MB
__device__ int    g_cnt2[2 * NN];

// ---------------------------------------------------------------------------
// Kernel 1: build CSC (both halves + zero-fill). One thread per column.
// ---------------------------------------------------------------------------
__global__ void __launch_bounds__(128) build_pack_kernel(const float* __restrict__ W) {
    const int n = blockIdx.x * blockDim.x + threadIdx.x;
    if (n >= NN) return;
#pragma unroll
    for (int h = 0; h < 2; ++h) {
        int c = 0;
        for (int k = 0; k < HALF_K; ++k) {
            const float w = W[(size_t)(h * HALF_K + k) * NN + n];
            if (w != 0.0f) {
                if (c < HSLOTS)
                    g_pairT[(size_t)(h * HSLOTS + c) * NN + n] =
                        make_float2(w, __int_as_float(k));
                ++c;
            }
        }
        const int cc = (c < HSLOTS) ? c : HSLOTS;
        for (int s = cc; s < HSLOTS; ++s)
            g_pairT[(size_t)(h * HSLOTS + s) * NN + n] = make_float2(0.f, 0.f);
        g_cnt2[h * NN + n] = cc;
    }
}

// ---------------------------------------------------------------------------
// Kernel 2: sparse GEMM  out = relu(x @ W + bias), dense output.
// 512 threads / 16 warps; warp owns 8 columns, lane owns 4 consecutive rows.
// K split in two halves; per half: stage x[kh][128r] + interleaved pair tile,
// then accumulate. Pair reads = uniform LDS.128 broadcast (2 pairs each).
// ---------------------------------------------------------------------------
__global__ void __launch_bounds__(GEMM_THREADS, 2) gemm_kernel(
    const float* __restrict__ x,
    const float* __restrict__ bias,
    float* __restrict__ out)
{
    extern __shared__ float sm[];
    float*  xs   = sm;                           // [HALF_K][XS_STRIDE]
    float4* pp4  = (float4*)(sm + PP_OFF);       // [NSP][TC] (2 pairs per f4)
    float2* pp2  = (float2*)pp4;
    int*    scnt = (int*)(sm + SCNT_OFF);        // [TC] padded counts

    const int row0 = blockIdx.y * TR;
    const int col0 = blockIdx.x * TC;
    const int tid  = threadIdx.x;
    const int warp = tid >> 5;
    const int lane = tid & 31;
    const int rbase = lane << 2;

    float4 acc[8];
#pragma unroll
    for (int cc = 0; cc < 8; ++cc) acc[cc] = make_float4(0.f, 0.f, 0.f, 0.f);

    for (int h = 0; h < 2; ++h) {
        // stage x half-tile transposed: xs[k][r]  (gmem coalesced over k)
        for (int u = tid; u < TR * HALF_K; u += GEMM_THREADS) {
            const int r = u >> 7;            // 0..127
            const int k = u & 127;           // 0..127
            xs[k * XS_STRIDE + r] = x[(size_t)(row0 + r) * K_DIM + h * HALF_K + k];
        }
        // stage pair tile, interleaving slot pairs into float4 lanes
        for (int u = tid; u < HSLOTS * TC; u += GEMM_THREADS) {
            const int s = u >> 7;            // slot 0..39
            const int c = u & 127;
            const float2 f = g_pairT[(size_t)(h * HSLOTS + s) * NN + col0 + c];
            pp2[((s >> 1) * TC + c) * 2 + (s & 1)] = f;
        }
        if (tid < TC) scnt[tid] = (g_cnt2[h * NN + col0 + tid] + 3) & ~3;
        __syncthreads();

#pragma unroll
        for (int cc = 0; cc < 8; ++cc) {
            const int c = (warp << 3) + cc;
            const int cntp = scnt[c];
            const float4* ppc = pp4 + c;
            float4 a = acc[cc];
            for (int j = 0; j < cntp; j += 4) {
                const int sp = j >> 1;
                const float4 q0 = ppc[(sp + 0) * TC];   // pairs j, j+1
                const float4 q1 = ppc[(sp + 1) * TC];   // pairs j+2, j+3
                {
                    const int k = __float_as_int(q0.y);
                    const float4 xv = *(const float4*)(xs + k * XS_STRIDE + rbase);
                    a.x = fmaf(xv.x, q0.x, a.x); a.y = fmaf(xv.y, q0.x, a.y);
                    a.z = fmaf(xv.z, q0.x, a.z); a.w = fmaf(xv.w, q0.x, a.w);
                }
                {
                    const int k = __float_as_int(q0.w);
                    const float4 xv = *(const float4*)(xs + k * XS_STRIDE + rbase);
                    a.x = fmaf(xv.x, q0.z, a.x); a.y = fmaf(xv.y, q0.z, a.y);
                    a.z = fmaf(xv.z, q0.z, a.z); a.w = fmaf(xv.w, q0.z, a.w);
                }
                {
                    const int k = __float_as_int(q1.y);
                    const float4 xv = *(const float4*)(xs + k * XS_STRIDE + rbase);
                    a.x = fmaf(xv.x, q1.x, a.x); a.y = fmaf(xv.y, q1.x, a.y);
                    a.z = fmaf(xv.z, q1.x, a.z); a.w = fmaf(xv.w, q1.x, a.w);
                }
                {
                    const int k = __float_as_int(q1.w);
                    const float4 xv = *(const float4*)(xs + k * XS_STRIDE + rbase);
                    a.x = fmaf(xv.x, q1.z, a.x); a.y = fmaf(xv.y, q1.z, a.y);
                    a.z = fmaf(xv.z, q1.z, a.z); a.w = fmaf(xv.w, q1.z, a.w);
                }
            }
            acc[cc] = a;
        }
        __syncthreads();                     // xs/pp reads done before refill
    }

    // epilogue: bias + relu -> smem transpose buffer (overlays xs) -> flush
    float* os = sm;                          // [TR][OS_STRIDE]
#pragma unroll
    for (int cc = 0; cc < 8; ++cc) {
        const int c = (warp << 3) + cc;
        const float b = __ldg(bias + col0 + c);
        os[(rbase + 0) * OS_STRIDE + c] = fmaxf(acc[cc].x + b, 0.f);
        os[(rbase + 1) * OS_STRIDE + c] = fmaxf(acc[cc].y + b, 0.f);
        os[(rbase + 2) * OS_STRIDE + c] = fmaxf(acc[cc].z + b, 0.f);
        os[(rbase + 3) * OS_STRIDE + c] = fmaxf(acc[cc].w + b, 0.f);
    }
    __syncthreads();
    for (int l = tid; l < TR * TC; l += GEMM_THREADS) {
        const int r = l >> 7;
        const int c = l & 127;
        out[(size_t)(row0 + r) * NN + col0 + c] = os[r * OS_STRIDE + c];
    }
}

// ---------------------------------------------------------------------------
// Kernel 3: per-row exact top-K, 3 gmem reads + 1 write.
// Pass1: 12-bit histogram (bits[31:20], 4096 shared bins; zeros aggregated).
// Pass2: compact candidates in the threshold bin into smem; exact threshold
// + tie resolution on the small candidate list (no further full-row passes).
// Pass3: masked write-back. relu => uint compare is order-preserving.
// ---------------------------------------------------------------------------
#define CAP 2048

__global__ void __launch_bounds__(256) topk_kernel(float* __restrict__ out) {
    __shared__ int hist[4096];
    __shared__ unsigned int candv[CAP];
    __shared__ int candi[CAP];
    __shared__ int chunksum[256];
    __shared__ int eqix[512];
    __shared__ int s_b1, s_krem, s_cnt, s_need, s_m, s_eqcnt;
    __shared__ unsigned int s_tbits;

    const int t = threadIdx.x;
    const int lane = t & 31;
    float* rp = out + (size_t)blockIdx.x * NN;
    const uint4* rp4 = (const uint4*)rp;

    for (int i = t; i < 4096; i += 256) hist[i] = 0;
    if (t == 0) { s_cnt = 0; s_eqcnt = 0; }
    __syncthreads();

    // ---- pass 1: 12-bit histogram ----
    {
        int zc = 0;
        for (int i = t; i < NN / 4; i += 256) {
            const uint4 q = rp4[i];
            if (q.x) atomicAdd(&hist[q.x >> 20], 1); else ++zc;
            if (q.y) atomicAdd(&hist[q.y >> 20], 1); else ++zc;
            if (q.z) atomicAdd(&hist[q.z >> 20], 1); else ++zc;
            if (q.w) atomicAdd(&hist[q.w >> 20], 1); else ++zc;
        }
#pragma unroll
        for (int off = 16; off; off >>= 1) zc += __shfl_down_sync(0xffffffffu, zc, off);
        if (lane == 0 && zc) atomicAdd(&hist[0], zc);
    }
    __syncthreads();
    { int s = 0; for (int k = 0; k < 16; ++k) s += hist[t * 16 + k]; chunksum[t] = s; }
    __syncthreads();
    if (t == 0) {
        int kr = KTOP, c = 255;
        for (;; --c) { const int h = chunksum[c]; if (h >= kr) break; kr -= h; }
        int b = c * 16 + 15;
        for (;; --b) { const int h = hist[b]; if (h >= kr) break; kr -= h; }
        s_b1 = b; s_krem = kr;
    }
    __syncthreads();
    const int b1 = s_b1;
    const int krem = s_krem;

    unsigned int tbits = 0u;
    int need = 0, m = 0;
    bool keep_all = true;

    if (b1 != 0) {
        // ---- pass 2: compact threshold-bin candidates ----
        for (int i = t; i < NN / 4; i += 256) {
            const uint4 q = rp4[i];
            const int base = i * 4;
            if ((int)(q.x >> 20) == b1) { const int p = atomicAdd(&s_cnt, 1); if (p < CAP) { candv[p] = q.x; candi[p] = base + 0; } }
            if ((int)(q.y >> 20) == b1) { const int p = atomicAdd(&s_cnt, 1); if (p < CAP) { candv[p] = q.y; candi[p] = base + 1; } }
            if ((int)(q.z >> 20) == b1) { const int p = atomicAdd(&s_cnt, 1); if (p < CAP) { candv[p] = q.z; candi[p] = base + 2; } }
            if ((int)(q.w >> 20) == b1) { const int p = atomicAdd(&s_cnt, 1); if (p < CAP) { candv[p] = q.w; candi[p] = base + 3; } }
        }
        __syncthreads();
        const int cnt = s_cnt;
        if (cnt > CAP) {
            // practically unreachable fallback: keep the whole bin
            tbits = ((unsigned int)b1 << 20) - 1u;
            keep_all = true;
        } else {
            // exact krem-th largest among candidates (O(cnt^2/256) smem work)
            for (int i = t; i < cnt; i += 256) {
                const unsigned int u = candv[i];
                int g = 0, e = 0;
                for (int j = 0; j < cnt; ++j) {
                    const unsigned int v = candv[j];
                    g += (v > u); e += (v == u);
                }
                if (g < krem && krem <= g + e) { s_tbits = u; s_need = krem - g; s_m = e; }
            }
            __syncthreads();
            tbits = s_tbits; need = s_need; m = s_m;
            keep_all = (need >= m) || (m > 512);
            if (!keep_all) {
                for (int i = t; i < cnt; i += 256)
                    if (candv[i] == tbits) { const int p = atomicAdd(&s_eqcnt, 1); if (p < 512) eqix[p] = candi[i]; }
                __syncthreads();
            }
        }
    }
    // b1 == 0: tbits stays 0 -> keep all positives (kept "zeros" write 0 anyway)

    // ---- pass 3: masked write-back ----
    uint4* wp4 = (uint4*)rp;
    for (int i = t; i < NN / 4; i += 256) {
        uint4 q = rp4[i];
        const int base = i * 4;
        unsigned int* pc = (unsigned int*)&q;
#pragma unroll
        for (int c = 0; c < 4; ++c) {
            const unsigned int u = pc[c];
            unsigned int r = 0u;
            if (u > tbits) {
                r = u;
            } else if (u == tbits && tbits != 0u) {
                if (keep_all) {
                    r = u;
                } else {
                    int rank = 0;
                    for (int qq = 0; qq < m; ++qq) rank += (eqix[qq] < base + c);
                    if (rank < need) r = u;
                }
            }
            pc[c] = r;
        }
        wp4[i] = q;
    }
}

// ---------------------------------------------------------------------------
// Launch
// ---------------------------------------------------------------------------
extern "C" void kernel_launch(void* const* d_in, const int* in_sizes, int n_in,
                              void* d_out, int out_size)
{
    const float* x = nullptr;
    const float* W = nullptr;
    const float* bias = nullptr;
    for (int i = 0; i < n_in; ++i) {
        if (in_sizes[i] == M_ROWS * K_DIM)      x = (const float*)d_in[i];
        else if (in_sizes[i] == K_DIM * NN)     W = (const float*)d_in[i];
        else if (in_sizes[i] == NN)             bias = (const float*)d_in[i];
    }
    float* out = (float*)d_out;

    cudaFuncSetAttribute(gemm_kernel, cudaFuncAttributeMaxDynamicSharedMemorySize, GEMM_SMEM);

    build_pack_kernel<<<NN / 128, 128>>>(W);

    dim3 ggrid(NN / TC, M_ROWS / TR);        // 128 x 32 = 4096 tiles
    gemm_kernel<<<ggrid, GEMM_THREADS, GEMM_SMEM>>>(x, bias, out);

    topk_kernel<<<M_ROWS, 256>>>(out);
}